// round 11
// baseline (speedup 1.0000x reference)
#include <cuda_runtime.h>
#include <cuda_bf16.h>
#include <cstdint>

#define NN 8192

// ---------------- scratch (device globals; no allocations) ------------------
__device__ __align__(128) uint32_t g_adjbits[(size_t)NN * 256];     // 8 MB bitmask
__device__ float g_invdeg[NN];
__device__ __align__(128) __nv_bfloat16 g_xT[(size_t)256 * NN];     // x^T bf16
__device__ __align__(128) __nv_bfloat16 g_nx_hi[(size_t)NN * 512];  // [x1|x] hi
__device__ __align__(128) __nv_bfloat16 g_nx_lo[(size_t)NN * 512];  // [x1|x] lo
__device__ __align__(128) __nv_bfloat16 g_Wt_hi[768 * 512];         // W^T hi
__device__ __align__(128) __nv_bfloat16 g_Wt_lo[768 * 512];         // W^T lo

// ---------------- helpers ----------------------------------------------------
__device__ __forceinline__ uint32_t smem_u32(const void* p) {
    uint32_t a;
    asm("{ .reg .u64 t; cvta.to.shared.u64 t, %1; cvt.u32.u64 %0, t; }"
        : "=r"(a) : "l"(p));
    return a;
}
__device__ __forceinline__ void cp16(uint32_t dst, const void* src) {
    asm volatile("cp.async.cg.shared.global [%0], [%1], 16;" :: "r"(dst), "l"(src));
}
__device__ __forceinline__ void cp_commit() {
    asm volatile("cp.async.commit_group;" ::: "memory");
}
template <int N> __device__ __forceinline__ void cp_wait() {
    asm volatile("cp.async.wait_group %0;" :: "n"(N) : "memory");
}
__device__ __forceinline__ void sts16(uint32_t addr, uint32_t v0, uint32_t v1,
                                      uint32_t v2, uint32_t v3) {
    asm volatile("st.shared.v4.u32 [%0], {%1,%2,%3,%4};"
                 :: "r"(addr), "r"(v0), "r"(v1), "r"(v2), "r"(v3) : "memory");
}
__device__ __forceinline__ void ldsm4(uint32_t& r0, uint32_t& r1, uint32_t& r2,
                                      uint32_t& r3, uint32_t addr) {
    asm volatile("ldmatrix.sync.aligned.m8n8.x4.shared.b16 {%0,%1,%2,%3}, [%4];"
                 : "=r"(r0), "=r"(r1), "=r"(r2), "=r"(r3) : "r"(addr));
}
__device__ __forceinline__ void mma16816(float* c, const uint32_t* a,
                                         const uint32_t* b) {
    asm volatile(
        "mma.sync.aligned.m16n8k16.row.col.f32.bf16.bf16.f32 "
        "{%0,%1,%2,%3}, {%4,%5,%6,%7}, {%8,%9}, {%0,%1,%2,%3};"
        : "+f"(c[0]), "+f"(c[1]), "+f"(c[2]), "+f"(c[3])
        : "r"(a[0]), "r"(a[1]), "r"(a[2]), "r"(a[3]), "r"(b[0]), "r"(b[1]));
}

// generic warp-tile compute for gemm2 path: 32(M) x 64(N) x (KK*16)(K)
template <int KK, int PITCH>
__device__ __forceinline__ void tile_compute(uint32_t aAddr, uint32_t bAddr,
                                             float (&c)[2][8][4]) {
#pragma unroll
    for (int kk = 0; kk < KK; ++kk) {
        uint32_t A[2][4], B[8][2];
        ldsm4(A[0][0], A[0][1], A[0][2], A[0][3], aAddr + kk * 32);
        ldsm4(A[1][0], A[1][1], A[1][2], A[1][3], aAddr + 16 * PITCH + kk * 32);
#pragma unroll
        for (int p = 0; p < 4; ++p) {
            uint32_t r0, r1, r2, r3;
            ldsm4(r0, r1, r2, r3, bAddr + p * 16 * PITCH + kk * 32);
            B[2 * p][0] = r0; B[2 * p][1] = r1;
            B[2 * p + 1][0] = r2; B[2 * p + 1][1] = r3;
        }
#pragma unroll
        for (int mt = 0; mt < 2; ++mt)
#pragma unroll
            for (int nt = 0; nt < 8; ++nt)
                mma16816(c[mt][nt], A[mt], B[nt]);
    }
}

// ---------------- conv: adj int32 -> bitmask + inv degree --------------------
__global__ void __launch_bounds__(256) k_conv(const int* __restrict__ adj) {
    __shared__ int wsum[8];
    const int row = blockIdx.x;
    const int lane = threadIdx.x & 31, w = threadIdx.x >> 5;
    const int* src = adj + (size_t)row * NN + w * 1024 + lane;
    uint32_t* dst = g_adjbits + (size_t)row * 256 + w * 32;
    int cnt = 0;
#pragma unroll 8
    for (int p = 0; p < 32; ++p) {
        int v = src[p * 32];
        uint32_t b = __ballot_sync(0xFFFFFFFFu, v == 1);
        if (lane == 0) { dst[p] = b; cnt += __popc(b); }
    }
    if (lane == 0) wsum[w] = cnt;
    __syncthreads();
    if (threadIdx.x == 0) {
        int t = 0;
#pragma unroll
        for (int i = 0; i < 8; ++i) t += wsum[i];
        g_invdeg[row] = 1.0f / (float)t;
    }
}

// ---------------- prep kernels ----------------------------------------------
__global__ void k_prep_x(const float* __restrict__ x) {
    __shared__ float tile[32][33];
    const int n0 = blockIdx.x * 32, f0 = blockIdx.y * 32;
    const int tx = threadIdx.x, ty = threadIdx.y;
    float v = x[(size_t)(n0 + ty) * 256 + f0 + tx];
    tile[ty][tx] = v;
    __nv_bfloat16 h = __float2bfloat16(v);
    size_t o = (size_t)(n0 + ty) * 512 + 256 + f0 + tx;
    g_nx_hi[o] = h;
    g_nx_lo[o] = __float2bfloat16(v - __bfloat162float(h));
    __syncthreads();
    g_xT[(size_t)(f0 + ty) * NN + n0 + tx] = __float2bfloat16(tile[tx][ty]);
}

__global__ void k_prep_w(const float* __restrict__ w) {
    const int b = blockIdx.x;            // Wt row = k*256 + o
    const int k = b >> 8, o = b & 255;
    const float* src = w + (size_t)k * 512 * 256 + o;
    __nv_bfloat16* dh = g_Wt_hi + (size_t)b * 512;
    __nv_bfloat16* dl = g_Wt_lo + (size_t)b * 512;
    for (int f = threadIdx.x; f < 512; f += 256) {
        float v = src[(size_t)f * 256];
        __nv_bfloat16 h = __float2bfloat16(v);
        dh[f] = h;
        dl[f] = __float2bfloat16(v - __bfloat162float(h));
    }
}

// ---------------- GEMM1: x1 = (adj @ x) / deg --------------------------------
// grid 128 = 64 M-tiles x 2 N-tiles, 256 threads (8 warps, 4m x 2n grid).
// CTA tile 128x128, warp tile 32x64. K = 8192 in 64 chunks of 128.
// A: bits expanded cooperatively into smem bf16 tile (double-buffered).
// B: g_xT via 4-stage cp.async. Inner loop: double-buffered fragments.
#define PITCH1 272u
#define ASTG1  34816u            // A stage: 128 rows * 272
#define ABUF   69632u            // 2 A stages; B starts here
#define BSTG1  34816u            // 4 B stages -> total 208896 B

__device__ __forceinline__ void g1_cpB(uint32_t sbase, int s, int kc, int n0,
                                       int tid) {
    const int row = tid >> 1, half = tid & 1;
    const uint32_t dst = sbase + ABUF + s * BSTG1 + row * PITCH1 + half * 128;
    const char* src = (const char*)(g_xT + (size_t)(n0 + row) * NN + kc * 128) +
                      half * 128;
#pragma unroll
    for (int j = 0; j < 8; ++j) cp16(dst + j * 16, src + j * 16);
}

// expand two 32-bit words (64 K-cols of one M-row) into 128B of bf16 smem
__device__ __forceinline__ void g1_expand(uint32_t sbase, int s, int tid,
                                          uint2 bw2) {
    const uint32_t base = sbase + s * ASTG1 + (tid >> 1) * PITCH1 + (tid & 1) * 128;
#pragma unroll
    for (int w = 0; w < 2; ++w) {
        const uint32_t bw = w ? bw2.y : bw2.x;
#pragma unroll
        for (int q = 0; q < 4; ++q) {
            uint32_t w0 = ((bw >> (8*q+0)) & 1u) * 0x3F80u | ((bw >> (8*q+1)) & 1u) * 0x3F800000u;
            uint32_t w1 = ((bw >> (8*q+2)) & 1u) * 0x3F80u | ((bw >> (8*q+3)) & 1u) * 0x3F800000u;
            uint32_t w2 = ((bw >> (8*q+4)) & 1u) * 0x3F80u | ((bw >> (8*q+5)) & 1u) * 0x3F800000u;
            uint32_t w3 = ((bw >> (8*q+6)) & 1u) * 0x3F80u | ((bw >> (8*q+7)) & 1u) * 0x3F800000u;
            sts16(base + w * 64 + q * 16, w0, w1, w2, w3);
        }
    }
}

__device__ __forceinline__ void g1_ldA(uint32_t aA, int kk, uint32_t (&Af)[2][4]) {
    ldsm4(Af[0][0], Af[0][1], Af[0][2], Af[0][3], aA + kk * 32);
    ldsm4(Af[1][0], Af[1][1], Af[1][2], Af[1][3], aA + 16 * PITCH1 + kk * 32);
}
__device__ __forceinline__ void g1_ldB(uint32_t bA, int kk, uint32_t (&Bf)[8][2]) {
#pragma unroll
    for (int p = 0; p < 4; ++p) {
        uint32_t r0, r1, r2, r3;
        ldsm4(r0, r1, r2, r3, bA + p * (16 * PITCH1) + kk * 32);
        Bf[2 * p][0] = r0; Bf[2 * p][1] = r1;
        Bf[2 * p + 1][0] = r2; Bf[2 * p + 1][1] = r3;
    }
}

__global__ void __launch_bounds__(256, 1) k_gemm1() {
    extern __shared__ char smem[];
    const uint32_t sbase = smem_u32(smem);
    const int tid = threadIdx.x, lane = tid & 31, wid = tid >> 5;
    const int wm = wid >> 1, wn = wid & 1;       // 4 x 2 warp grid
    const int m0 = (blockIdx.x >> 1) * 128, n0 = (blockIdx.x & 1) * 128;

    // this thread's bit stream: row m0+(tid>>1), word pair (it*4 + (tid&1)*2)
    const uint32_t* bitp = g_adjbits + (size_t)(m0 + (tid >> 1)) * 256 + (tid & 1) * 2;

    uint2 bits_cur = *(const uint2*)bitp;
    g1_cpB(sbase, 0, 0, n0, tid); cp_commit();
    g1_cpB(sbase, 1, 1, n0, tid); cp_commit();
    g1_cpB(sbase, 2, 2, n0, tid); cp_commit();
    g1_expand(sbase, 0, tid, bits_cur);          // A stage 0 (it=0)
    bits_cur = *(const uint2*)(bitp + 4);        // bits for it=1

    const uint32_t aAddr0 = sbase + (wm * 32 + (lane & 15)) * PITCH1 + (lane >> 4) * 16;
    const uint32_t bAddr0 = sbase + ABUF +
        (wn * 64 + ((lane >> 4) << 3) + (lane & 7)) * PITCH1 + ((lane >> 3) & 1) * 16;

    float c[2][8][4] = {};
    for (int it = 0; it < 64; ++it) {
        cp_wait<2>();
        __syncthreads();            // B stage it&3 ready; A stage it&1 written
        if (it + 3 < 64) g1_cpB(sbase, (it + 3) & 3, it + 3, n0, tid);
        cp_commit();
        if (it + 1 < 64) g1_expand(sbase, (it + 1) & 1, tid, bits_cur);
        if (it + 2 < 64) bits_cur = *(const uint2*)(bitp + (it + 2) * 4);

        const uint32_t aA = aAddr0 + (it & 1) * ASTG1;
        const uint32_t bA = bAddr0 + (it & 3) * BSTG1;

        // double-buffered fragment pipeline over kk
        uint32_t Af[2][2][4], Bf[2][8][2];
        g1_ldA(aA, 0, Af[0]);
        g1_ldB(bA, 0, Bf[0]);
#pragma unroll
        for (int kk = 0; kk < 8; ++kk) {
            const int cur = kk & 1;
            if (kk < 7) {
                g1_ldA(aA, kk + 1, Af[cur ^ 1]);
                g1_ldB(bA, kk + 1, Bf[cur ^ 1]);
            }
#pragma unroll
            for (int mt = 0; mt < 2; ++mt)
#pragma unroll
                for (int nt = 0; nt < 8; ++nt)
                    mma16816(c[mt][nt], Af[cur][mt], Bf[cur][nt]);
        }
    }

    // epilogue: /deg, hi/lo bf16 split into g_nx
    const int r = lane >> 2, q = lane & 3;
#pragma unroll
    for (int mt = 0; mt < 2; ++mt) {
        const int lr = wm * 32 + mt * 16 + r;
        const float inv0 = g_invdeg[m0 + lr];
        const float inv1 = g_invdeg[m0 + lr + 8];
        const size_t gm0 = (size_t)(m0 + lr), gm1 = gm0 + 8;
#pragma unroll
        for (int nt = 0; nt < 8; ++nt) {
            const int col = n0 + wn * 64 + nt * 8 + q * 2;
            float v0 = c[mt][nt][0] * inv0, v1 = c[mt][nt][1] * inv0;
            float v2 = c[mt][nt][2] * inv1, v3 = c[mt][nt][3] * inv1;
            __nv_bfloat16 h0 = __float2bfloat16(v0), h1 = __float2bfloat16(v1);
            __nv_bfloat16 h2 = __float2bfloat16(v2), h3 = __float2bfloat16(v3);
            *(uint32_t*)(g_nx_hi + gm0 * 512 + col) =
                ((uint32_t)__bfloat16_as_ushort(h1) << 16) | __bfloat16_as_ushort(h0);
            *(uint32_t*)(g_nx_hi + gm1 * 512 + col) =
                ((uint32_t)__bfloat16_as_ushort(h3) << 16) | __bfloat16_as_ushort(h2);
            __nv_bfloat16 l0 = __float2bfloat16(v0 - __bfloat162float(h0));
            __nv_bfloat16 l1 = __float2bfloat16(v1 - __bfloat162float(h1));
            __nv_bfloat16 l2 = __float2bfloat16(v2 - __bfloat162float(h2));
            __nv_bfloat16 l3 = __float2bfloat16(v3 - __bfloat162float(h3));
            *(uint32_t*)(g_nx_lo + gm0 * 512 + col) =
                ((uint32_t)__bfloat16_as_ushort(l1) << 16) | __bfloat16_as_ushort(l0);
            *(uint32_t*)(g_nx_lo + gm1 * 512 + col) =
                ((uint32_t)__bfloat16_as_ushort(l3) << 16) | __bfloat16_as_ushort(l2);
        }
    }
}

// ---------------- GEMM2: out[k] = nx @ W[k] + bias (3-term bf16 split) ------
// (unchanged: 66.6us measured)
#define ROWB   80u
#define STG    10240u
#define BOFF   40960u

__device__ __forceinline__ void g2_cp(uint32_t sbase, int s, int it, int m0,
                                      int bn0, int tid) {
    const __nv_bfloat16 *Ap, *Bp;
    int f0;
    if (it < 16)      { Ap = g_nx_hi; Bp = g_Wt_hi; f0 = it * 32; }
    else if (it < 32) { Ap = g_nx_hi; Bp = g_Wt_lo; f0 = (it - 16) * 32; }
    else              { Ap = g_nx_lo; Bp = g_Wt_hi; f0 = 256 + (it - 32) * 32; }
#pragma unroll
    for (int i = 0; i < 2; ++i) {
        int idx = tid + i * 256;
        int rr = idx >> 2, cc = idx & 3;
        cp16(sbase + s * STG + rr * ROWB + cc * 16,
             Ap + (size_t)(m0 + rr) * 512 + f0 + cc * 8);
        cp16(sbase + BOFF + s * STG + rr * ROWB + cc * 16,
             Bp + (size_t)(bn0 + rr) * 512 + f0 + cc * 8);
    }
}

__global__ void __launch_bounds__(256, 2) k_gemm2(const float* __restrict__ bias,
                                                  float* __restrict__ out) {
    extern __shared__ char smem[];
    __shared__ float sbias[128];
    const uint32_t sbase = smem_u32(smem);
    const int tid = threadIdx.x, lane = tid & 31, wid = tid >> 5;
    const int wm = wid >> 1, wn = wid & 1;
    const int bx = blockIdx.x;
    const int m0 = (bx / 6) * 128;
    const int ntile = bx % 6;
    const int kh = ntile >> 1, o0 = (ntile & 1) * 128;
    const int bn0 = kh * 256 + o0;
    if (tid < 128) sbias[tid] = bias[o0 + tid];

    g2_cp(sbase, 0, 0, m0, bn0, tid); cp_commit();
    g2_cp(sbase, 1, 1, m0, bn0, tid); cp_commit();
    g2_cp(sbase, 2, 2, m0, bn0, tid); cp_commit();

    const uint32_t aAddr0 = sbase + (wm * 32 + (lane & 15)) * ROWB + (lane >> 4) * 16;
    const uint32_t bAddr0 = sbase + BOFF +
        (wn * 64 + ((lane >> 4) << 3) + (lane & 7)) * ROWB + ((lane >> 3) & 1) * 16;

    float c[2][8][4] = {};
    for (int it = 0; it < 40; ++it) {
        const int s = it & 3;
        cp_wait<2>();
        __syncthreads();
        if (it + 3 < 40) g2_cp(sbase, (it + 3) & 3, it + 3, m0, bn0, tid);
        cp_commit();
        tile_compute<2, ROWB>(aAddr0 + s * STG, bAddr0 + s * STG, c);
    }

    const int r = lane >> 2, q = lane & 3;
#pragma unroll
    for (int mt = 0; mt < 2; ++mt) {
        const int lr = wm * 32 + mt * 16 + r;
        const size_t gm0 = (size_t)(m0 + lr);
#pragma unroll
        for (int nt = 0; nt < 8; ++nt) {
            const int oc = wn * 64 + nt * 8 + q * 2;
            float2 va = make_float2(c[mt][nt][0] + sbias[oc],
                                    c[mt][nt][1] + sbias[oc + 1]);
            float2 vb = make_float2(c[mt][nt][2] + sbias[oc],
                                    c[mt][nt][3] + sbias[oc + 1]);
            *(float2*)(out + ((size_t)kh * NN + gm0) * 256 + o0 + oc) = va;
            *(float2*)(out + ((size_t)kh * NN + gm0 + 8) * 256 + o0 + oc) = vb;
        }
    }
}

// ---------------- launch -----------------------------------------------------
extern "C" void kernel_launch(void* const* d_in, const int* in_sizes, int n_in,
                              void* d_out, int out_size) {
    const float* x = nullptr;
    const int* adj = nullptr;
    const float* w = nullptr;
    const float* bias = nullptr;
    for (int i = 0; i < n_in; ++i) {
        long sz = in_sizes[i];
        if (sz == (long)NN * 256) x = (const float*)d_in[i];
        else if (sz == (long)NN * NN) adj = (const int*)d_in[i];
        else if (sz == 3L * 512 * 256) w = (const float*)d_in[i];
        else if (sz == 256) bias = (const float*)d_in[i];
    }
    float* out = (float*)d_out;

    cudaFuncSetAttribute(k_gemm1, cudaFuncAttributeMaxDynamicSharedMemorySize, 208896);
    cudaFuncSetAttribute(k_gemm2, cudaFuncAttributeMaxDynamicSharedMemorySize, 81920);

    k_prep_x<<<dim3(256, 8), dim3(32, 32)>>>(x);
    k_prep_w<<<768, 256>>>(w);
    k_conv<<<NN, 256>>>(adj);
    k_gemm1<<<128, 256, 208896>>>();
    k_gemm2<<<384, 256, 81920>>>(bias, out);
}

// round 12
// speedup vs baseline: 1.1042x; 1.1042x over previous
#include <cuda_runtime.h>
#include <cuda_bf16.h>
#include <cstdint>

#define NN 8192

// ---------------- scratch (device globals; no allocations) ------------------
__device__ __align__(128) uint32_t g_adjbits[(size_t)NN * 256];     // 8 MB bitmask
__device__ float g_invdeg[NN];
__device__ __align__(128) float g_x1a[(size_t)NN * 256];            // split-K half 0
__device__ __align__(128) float g_x1b[(size_t)NN * 256];            // split-K half 1
__device__ __align__(128) __nv_bfloat16 g_xT[(size_t)256 * NN];     // x^T bf16
__device__ __align__(128) __nv_bfloat16 g_nx_hi[(size_t)NN * 512];  // [x1|x] hi
__device__ __align__(128) __nv_bfloat16 g_nx_lo[(size_t)NN * 512];  // [x1|x] lo
__device__ __align__(128) __nv_bfloat16 g_Wt_hi[768 * 512];         // W^T hi
__device__ __align__(128) __nv_bfloat16 g_Wt_lo[768 * 512];         // W^T lo

// ---------------- helpers ----------------------------------------------------
__device__ __forceinline__ uint32_t smem_u32(const void* p) {
    uint32_t a;
    asm("{ .reg .u64 t; cvta.to.shared.u64 t, %1; cvt.u32.u64 %0, t; }"
        : "=r"(a) : "l"(p));
    return a;
}
__device__ __forceinline__ void cp16(uint32_t dst, const void* src) {
    asm volatile("cp.async.cg.shared.global [%0], [%1], 16;" :: "r"(dst), "l"(src));
}
__device__ __forceinline__ void cp_commit() {
    asm volatile("cp.async.commit_group;" ::: "memory");
}
template <int N> __device__ __forceinline__ void cp_wait() {
    asm volatile("cp.async.wait_group %0;" :: "n"(N) : "memory");
}
__device__ __forceinline__ void sts16(uint32_t addr, uint32_t v0, uint32_t v1,
                                      uint32_t v2, uint32_t v3) {
    asm volatile("st.shared.v4.u32 [%0], {%1,%2,%3,%4};"
                 :: "r"(addr), "r"(v0), "r"(v1), "r"(v2), "r"(v3) : "memory");
}
__device__ __forceinline__ void ldsm4(uint32_t& r0, uint32_t& r1, uint32_t& r2,
                                      uint32_t& r3, uint32_t addr) {
    asm volatile("ldmatrix.sync.aligned.m8n8.x4.shared.b16 {%0,%1,%2,%3}, [%4];"
                 : "=r"(r0), "=r"(r1), "=r"(r2), "=r"(r3) : "r"(addr));
}
__device__ __forceinline__ void mma16816(float* c, const uint32_t* a,
                                         const uint32_t* b) {
    asm volatile(
        "mma.sync.aligned.m16n8k16.row.col.f32.bf16.bf16.f32 "
        "{%0,%1,%2,%3}, {%4,%5,%6,%7}, {%8,%9}, {%0,%1,%2,%3};"
        : "+f"(c[0]), "+f"(c[1]), "+f"(c[2]), "+f"(c[3])
        : "r"(a[0]), "r"(a[1]), "r"(a[2]), "r"(a[3]), "r"(b[0]), "r"(b[1]));
}

// warp-tile compute: 32(M) x 64(N) x (KK*16)(K), accum c[2][8][4]
template <int KK, int PITCH>
__device__ __forceinline__ void tile_compute(uint32_t aAddr, uint32_t bAddr,
                                             float (&c)[2][8][4]) {
#pragma unroll
    for (int kk = 0; kk < KK; ++kk) {
        uint32_t A[2][4], B[8][2];
        ldsm4(A[0][0], A[0][1], A[0][2], A[0][3], aAddr + kk * 32);
        ldsm4(A[1][0], A[1][1], A[1][2], A[1][3], aAddr + 16 * PITCH + kk * 32);
#pragma unroll
        for (int p = 0; p < 4; ++p) {
            uint32_t r0, r1, r2, r3;
            ldsm4(r0, r1, r2, r3, bAddr + p * 16 * PITCH + kk * 32);
            B[2 * p][0] = r0; B[2 * p][1] = r1;
            B[2 * p + 1][0] = r2; B[2 * p + 1][1] = r3;
        }
#pragma unroll
        for (int mt = 0; mt < 2; ++mt)
#pragma unroll
            for (int nt = 0; nt < 8; ++nt)
                mma16816(c[mt][nt], A[mt], B[nt]);
    }
}

// ---------------- conv: adj int32 -> bitmask + inv degree --------------------
__global__ void __launch_bounds__(256) k_conv(const int* __restrict__ adj) {
    __shared__ int wsum[8];
    const int row = blockIdx.x;
    const int lane = threadIdx.x & 31, w = threadIdx.x >> 5;
    const int* src = adj + (size_t)row * NN + w * 1024 + lane;
    uint32_t* dst = g_adjbits + (size_t)row * 256 + w * 32;
    int cnt = 0;
#pragma unroll 8
    for (int p = 0; p < 32; ++p) {
        int v = src[p * 32];
        uint32_t b = __ballot_sync(0xFFFFFFFFu, v == 1);
        if (lane == 0) { dst[p] = b; cnt += __popc(b); }
    }
    if (lane == 0) wsum[w] = cnt;
    __syncthreads();
    if (threadIdx.x == 0) {
        int t = 0;
#pragma unroll
        for (int i = 0; i < 8; ++i) t += wsum[i];
        g_invdeg[row] = 1.0f / (float)t;
    }
}

// ---------------- prep kernels ----------------------------------------------
__global__ void k_prep_x(const float* __restrict__ x) {
    __shared__ float tile[32][33];
    const int n0 = blockIdx.x * 32, f0 = blockIdx.y * 32;
    const int tx = threadIdx.x, ty = threadIdx.y;
    float v = x[(size_t)(n0 + ty) * 256 + f0 + tx];
    tile[ty][tx] = v;
    __nv_bfloat16 h = __float2bfloat16(v);
    size_t o = (size_t)(n0 + ty) * 512 + 256 + f0 + tx;
    g_nx_hi[o] = h;
    g_nx_lo[o] = __float2bfloat16(v - __bfloat162float(h));
    __syncthreads();
    g_xT[(size_t)(f0 + ty) * NN + n0 + tx] = __float2bfloat16(tile[tx][ty]);
}

__global__ void k_prep_w(const float* __restrict__ w) {
    const int b = blockIdx.x;            // Wt row = k*256 + o
    const int k = b >> 8, o = b & 255;
    const float* src = w + (size_t)k * 512 * 256 + o;
    __nv_bfloat16* dh = g_Wt_hi + (size_t)b * 512;
    __nv_bfloat16* dl = g_Wt_lo + (size_t)b * 512;
    for (int f = threadIdx.x; f < 512; f += 256) {
        float v = src[(size_t)f * 256];
        __nv_bfloat16 h = __float2bfloat16(v);
        dh[f] = h;
        dl[f] = __float2bfloat16(v - __bfloat162float(h));
    }
}

// ---------------- GEMM1: split-K x2, 2 CTAs/SM -------------------------------
// grid 256 = 64 M-tiles x 2 N-tiles x 2 K-halves. 256 threads, 8 warps (4m x 2n).
// CTA tile 128x128, K-half 4096 in 64 chunks of 64. smem 108 KB -> 2 CTAs/SM.
// A: bits -> smem bf16 (double-buffered). B: g_xT via 4-stage cp.async.
#define P1   144u
#define AST  18432u              // A stage: 128 * 144
#define AB2  36864u              // 2 A stages; B base
#define BST  18432u              // 4 B stages -> total 110592

__device__ __forceinline__ void g1_cpB(uint32_t sbase, int s, int kc, int n0,
                                       int kz, int tid) {
    const int row = tid >> 1, half = tid & 1;
    const uint32_t dst = sbase + AB2 + s * BST + row * P1 + half * 64;
    const char* src = (const char*)(g_xT + (size_t)(n0 + row) * NN + kz * 4096 +
                                    kc * 64) + half * 64;
#pragma unroll
    for (int j = 0; j < 4; ++j) cp16(dst + j * 16, src + j * 16);
}

// expand one 32-bit word (32 K-cols of one M-row) into 64B of bf16 smem
__device__ __forceinline__ void g1_expand(uint32_t sbase, int s, int tid,
                                          uint32_t bw) {
    const uint32_t base = sbase + s * AST + (tid >> 1) * P1 + (tid & 1) * 64;
#pragma unroll
    for (int q = 0; q < 4; ++q) {
        uint32_t w0 = ((bw >> (8*q+0)) & 1u) * 0x3F80u | ((bw >> (8*q+1)) & 1u) * 0x3F800000u;
        uint32_t w1 = ((bw >> (8*q+2)) & 1u) * 0x3F80u | ((bw >> (8*q+3)) & 1u) * 0x3F800000u;
        uint32_t w2 = ((bw >> (8*q+4)) & 1u) * 0x3F80u | ((bw >> (8*q+5)) & 1u) * 0x3F800000u;
        uint32_t w3 = ((bw >> (8*q+6)) & 1u) * 0x3F80u | ((bw >> (8*q+7)) & 1u) * 0x3F800000u;
        sts16(base + q * 16, w0, w1, w2, w3);
    }
}

__global__ void __launch_bounds__(256, 2) k_gemm1() {
    extern __shared__ char smem[];
    const uint32_t sbase = smem_u32(smem);
    const int tid = threadIdx.x, lane = tid & 31, wid = tid >> 5;
    const int wm = wid >> 1, wn = wid & 1;       // 4m x 2n warp grid
    const int bx = blockIdx.x;
    const int m0 = (bx >> 2) * 128, n0 = (bx & 1) * 128, kz = (bx >> 1) & 1;

    // this thread's bit stream: row m0+(tid>>1), words kz*128 + it*2 + (tid&1)
    const uint32_t* bitp = g_adjbits + (size_t)(m0 + (tid >> 1)) * 256 +
                           kz * 128 + (tid & 1);

    uint32_t bits_cur = bitp[0];
    g1_cpB(sbase, 0, 0, n0, kz, tid); cp_commit();
    g1_cpB(sbase, 1, 1, n0, kz, tid); cp_commit();
    g1_cpB(sbase, 2, 2, n0, kz, tid); cp_commit();
    g1_expand(sbase, 0, tid, bits_cur);          // A stage 0 (it=0)
    bits_cur = bitp[2];                          // bits for it=1

    const uint32_t aAddr0 = sbase + (wm * 32 + (lane & 15)) * P1 + (lane >> 4) * 16;
    const uint32_t bAddr0 = sbase + AB2 +
        (wn * 64 + ((lane >> 4) << 3) + (lane & 7)) * P1 + ((lane >> 3) & 1) * 16;

    float c[2][8][4] = {};
    for (int it = 0; it < 64; ++it) {
        cp_wait<2>();
        __syncthreads();            // B stage it&3 ready; A stage it&1 written
        if (it + 3 < 64) g1_cpB(sbase, (it + 3) & 3, it + 3, n0, kz, tid);
        cp_commit();
        if (it + 1 < 64) g1_expand(sbase, (it + 1) & 1, tid, bits_cur);
        if (it + 2 < 64) bits_cur = bitp[(it + 2) * 2];

        tile_compute<4, P1>(aAddr0 + (it & 1) * AST,
                            bAddr0 + (it & 3) * BST, c);
    }

    // epilogue: raw fp32 partials to this K-half's buffer
    float* dst = kz ? g_x1b : g_x1a;
    const int r = lane >> 2, q = lane & 3;
#pragma unroll
    for (int mt = 0; mt < 2; ++mt) {
        const int lr = wm * 32 + mt * 16 + r;
        const size_t gm0 = (size_t)(m0 + lr), gm1 = gm0 + 8;
#pragma unroll
        for (int nt = 0; nt < 8; ++nt) {
            const int col = n0 + wn * 64 + nt * 8 + q * 2;
            *(float2*)(dst + gm0 * 256 + col) = make_float2(c[mt][nt][0], c[mt][nt][1]);
            *(float2*)(dst + gm1 * 256 + col) = make_float2(c[mt][nt][2], c[mt][nt][3]);
        }
    }
}

// ---------------- comb: x1 = (a+b)*invdeg -> nx hi/lo (cols 0..255) ----------
__global__ void __launch_bounds__(256) k_comb() {
    const int idx = blockIdx.x * 256 + threadIdx.x;      // float4 index
    const int row = idx >> 6;                             // 64 float4 per row
    const int col = (idx & 63) * 4;
    float4 a = ((const float4*)g_x1a)[idx];
    float4 b = ((const float4*)g_x1b)[idx];
    const float inv = g_invdeg[row];
    float v0 = (a.x + b.x) * inv, v1 = (a.y + b.y) * inv;
    float v2 = (a.z + b.z) * inv, v3 = (a.w + b.w) * inv;
    __nv_bfloat16 h0 = __float2bfloat16(v0), h1 = __float2bfloat16(v1);
    __nv_bfloat16 h2 = __float2bfloat16(v2), h3 = __float2bfloat16(v3);
    uint2 ph, pl;
    ph.x = ((uint32_t)__bfloat16_as_ushort(h1) << 16) | __bfloat16_as_ushort(h0);
    ph.y = ((uint32_t)__bfloat16_as_ushort(h3) << 16) | __bfloat16_as_ushort(h2);
    __nv_bfloat16 l0 = __float2bfloat16(v0 - __bfloat162float(h0));
    __nv_bfloat16 l1 = __float2bfloat16(v1 - __bfloat162float(h1));
    __nv_bfloat16 l2 = __float2bfloat16(v2 - __bfloat162float(h2));
    __nv_bfloat16 l3 = __float2bfloat16(v3 - __bfloat162float(h3));
    pl.x = ((uint32_t)__bfloat16_as_ushort(l1) << 16) | __bfloat16_as_ushort(l0);
    pl.y = ((uint32_t)__bfloat16_as_ushort(l3) << 16) | __bfloat16_as_ushort(l2);
    *(uint2*)(g_nx_hi + (size_t)row * 512 + col) = ph;
    *(uint2*)(g_nx_lo + (size_t)row * 512 + col) = pl;
}

// ---------------- GEMM2: out[k] = nx @ W[k] + bias (3-term bf16 split) ------
// (unchanged: 66.6us measured)
#define ROWB   80u
#define STG    10240u
#define BOFF   40960u

__device__ __forceinline__ void g2_cp(uint32_t sbase, int s, int it, int m0,
                                      int bn0, int tid) {
    const __nv_bfloat16 *Ap, *Bp;
    int f0;
    if (it < 16)      { Ap = g_nx_hi; Bp = g_Wt_hi; f0 = it * 32; }
    else if (it < 32) { Ap = g_nx_hi; Bp = g_Wt_lo; f0 = (it - 16) * 32; }
    else              { Ap = g_nx_lo; Bp = g_Wt_hi; f0 = 256 + (it - 32) * 32; }
#pragma unroll
    for (int i = 0; i < 2; ++i) {
        int idx = tid + i * 256;
        int rr = idx >> 2, cc = idx & 3;
        cp16(sbase + s * STG + rr * ROWB + cc * 16,
             Ap + (size_t)(m0 + rr) * 512 + f0 + cc * 8);
        cp16(sbase + BOFF + s * STG + rr * ROWB + cc * 16,
             Bp + (size_t)(bn0 + rr) * 512 + f0 + cc * 8);
    }
}

__global__ void __launch_bounds__(256, 2) k_gemm2(const float* __restrict__ bias,
                                                  float* __restrict__ out) {
    extern __shared__ char smem[];
    __shared__ float sbias[128];
    const uint32_t sbase = smem_u32(smem);
    const int tid = threadIdx.x, lane = tid & 31, wid = tid >> 5;
    const int wm = wid >> 1, wn = wid & 1;
    const int bx = blockIdx.x;
    const int m0 = (bx / 6) * 128;
    const int ntile = bx % 6;
    const int kh = ntile >> 1, o0 = (ntile & 1) * 128;
    const int bn0 = kh * 256 + o0;
    if (tid < 128) sbias[tid] = bias[o0 + tid];

    g2_cp(sbase, 0, 0, m0, bn0, tid); cp_commit();
    g2_cp(sbase, 1, 1, m0, bn0, tid); cp_commit();
    g2_cp(sbase, 2, 2, m0, bn0, tid); cp_commit();

    const uint32_t aAddr0 = sbase + (wm * 32 + (lane & 15)) * ROWB + (lane >> 4) * 16;
    const uint32_t bAddr0 = sbase + BOFF +
        (wn * 64 + ((lane >> 4) << 3) + (lane & 7)) * ROWB + ((lane >> 3) & 1) * 16;

    float c[2][8][4] = {};
    for (int it = 0; it < 40; ++it) {
        const int s = it & 3;
        cp_wait<2>();
        __syncthreads();
        if (it + 3 < 40) g2_cp(sbase, (it + 3) & 3, it + 3, m0, bn0, tid);
        cp_commit();
        tile_compute<2, ROWB>(aAddr0 + s * STG, bAddr0 + s * STG, c);
    }

    const int r = lane >> 2, q = lane & 3;
#pragma unroll
    for (int mt = 0; mt < 2; ++mt) {
        const int lr = wm * 32 + mt * 16 + r;
        const size_t gm0 = (size_t)(m0 + lr);
#pragma unroll
        for (int nt = 0; nt < 8; ++nt) {
            const int oc = wn * 64 + nt * 8 + q * 2;
            float2 va = make_float2(c[mt][nt][0] + sbias[oc],
                                    c[mt][nt][1] + sbias[oc + 1]);
            float2 vb = make_float2(c[mt][nt][2] + sbias[oc],
                                    c[mt][nt][3] + sbias[oc + 1]);
            *(float2*)(out + ((size_t)kh * NN + gm0) * 256 + o0 + oc) = va;
            *(float2*)(out + ((size_t)kh * NN + gm0 + 8) * 256 + o0 + oc) = vb;
        }
    }
}

// ---------------- launch -----------------------------------------------------
extern "C" void kernel_launch(void* const* d_in, const int* in_sizes, int n_in,
                              void* d_out, int out_size) {
    const float* x = nullptr;
    const int* adj = nullptr;
    const float* w = nullptr;
    const float* bias = nullptr;
    for (int i = 0; i < n_in; ++i) {
        long sz = in_sizes[i];
        if (sz == (long)NN * 256) x = (const float*)d_in[i];
        else if (sz == (long)NN * NN) adj = (const int*)d_in[i];
        else if (sz == 3L * 512 * 256) w = (const float*)d_in[i];
        else if (sz == 256) bias = (const float*)d_in[i];
    }
    float* out = (float*)d_out;

    cudaFuncSetAttribute(k_gemm1, cudaFuncAttributeMaxDynamicSharedMemorySize, 110592);
    cudaFuncSetAttribute(k_gemm2, cudaFuncAttributeMaxDynamicSharedMemorySize, 81920);

    k_prep_x<<<dim3(256, 8), dim3(32, 32)>>>(x);
    k_prep_w<<<768, 256>>>(w);
    k_conv<<<NN, 256>>>(adj);
    k_gemm1<<<256, 256, 110592>>>();
    k_comb<<<2048, 256>>>();
    k_gemm2<<<384, 256, 81920>>>(bias, out);
}